// round 11
// baseline (speedup 1.0000x reference)
#include <cuda_runtime.h>
#include <cstdint>

#define NT 256
#define TILE_ELTS 1024        // floats per staged tile (4 KB)
#define GRID 592              // 148 SMs x 4 CTAs

// Global accumulators (exclusive buckets 1..4). Zero at module load; last
// block resets them after finalizing -> each graph replay starts clean.
__device__ float        g_sums[4];
__device__ float        g_cnts[4];
__device__ unsigned int g_done;

// ---------------- asm helpers ----------------
__device__ __forceinline__ uint32_t smem_u32(const void* p) {
    uint32_t a;
    asm("{ .reg .u64 t; cvta.to.shared.u64 t, %1; cvt.u32.u64 %0, t; }"
        : "=r"(a) : "l"(p));
    return a;
}
__device__ __forceinline__ void bulk_s2g(void* gdst, uint32_t ssrc, uint32_t bytes) {
    asm volatile("cp.async.bulk.global.shared::cta.bulk_group [%0], [%1], %2;"
                 :: "l"(gdst), "r"(ssrc), "r"(bytes) : "memory");
}
__device__ __forceinline__ void bulk_commit() {
    asm volatile("cp.async.bulk.commit_group;" ::: "memory");
}
template <int N>
__device__ __forceinline__ void bulk_wait_read() {
    asm volatile("cp.async.bulk.wait_group.read %0;" :: "n"(N) : "memory");
}
__device__ __forceinline__ void bulk_wait_all() {
    asm volatile("cp.async.bulk.wait_group 0;" ::: "memory");
}
__device__ __forceinline__ void fence_async() {
    asm volatile("fence.proxy.async.shared::cta;" ::: "memory");
}

// ---------------- math (unchanged since R5) ----------------
// Exclusive buckets: b1=[-1,-0.5) b2=[-0.5,0) b3=[0,0.5) b4=[0.5,1].
// Class-mask bit-exact vs reference; boundary attribution effect <= 1e-6 rel.
__device__ __forceinline__ void classify(float pv, float rv,
                                         float s[4], float c[4], float& om) {
    float d  = fabsf(pv - rv);
    bool  m0 = (rv >= -1.0f) && (rv <= 1.0f);
    bool  b  = (rv >= -0.5f);
    bool  cc = (rv >=  0.0f);
    bool  dd = (rv >=  0.5f);

    bool q1 = m0 && !b;
    bool q2 = m0 && b && !cc;
    bool q3 = m0 && cc && !dd;
    bool q4 = m0 && dd;

    if (q1) { s[0] += d; c[0] += 1.0f; }
    if (q2) { s[1] += d; c[1] += 1.0f; }
    if (q3) { s[2] += d; c[2] += 1.0f; }
    if (q4) { s[3] += d; c[3] += 1.0f; }

    float t = -0.5f;
    if (b)  t += 0.5f;
    if (cc) t += 0.5f;
    if (dd) t += 0.5f;
    om = m0 ? t : -1.0f;
}

__device__ __forceinline__ void proc4(float4 p, float4 r,
                                      float s[4], float c[4], float om[4]) {
    classify(p.x, r.x, s, c, om[0]);
    classify(p.y, r.y, s, c, om[1]);
    classify(p.z, r.z, s, c, om[2]);
    classify(p.w, r.w, s, c, om[3]);
}

// ---------------- kernel ----------------
// Staged tile tau covers mask elements [2 + 1024*tau, 2 + 1024*(tau+1)):
// gmem byte addr of tile = out + 24 + 8 + 4096*tau  -> 16B aligned (out is
// 256B aligned), size 4096 -> valid TMA bulk store. Reads stay on aligned
// float4 groups; thread j of tile tau computes group g = 256*tau + j, whose
// om[k] lands at tile slot 4j+k-2 (thread 0's om[0..1] roll into the
// PREVIOUS tile's slots 1022/1023). Chunk boundaries are patched by an
// om-only "closing group" (no accumulation -> each element accumulated
// exactly once globally). Head elements 0,1 and the final tile use direct
// streaming stores.
__global__ void __launch_bounds__(NT, 4) mcl_bulk_kernel(
    const float* __restrict__ pre,
    const float* __restrict__ real,
    float* __restrict__ out,
    int tiles_total,               // n / 1024
    int n)
{
    __shared__ float stg[3][TILE_ELTS];   // 12 KB triple buffer

    const int tid = threadIdx.x;
    const int b   = blockIdx.x;

    // Tile partition over GRID CTAs.
    const int per = tiles_total / GRID;
    const int rem = tiles_total % GRID;
    const int ts  = b * per + (b < rem ? b : rem);
    const int te  = ts + per + (b < rem ? 1 : 0);
    const int last_tile  = tiles_total - 1;          // stored directly
    const int te_staged  = te < last_tile ? te : last_tile;

    const float4* p4 = reinterpret_cast<const float4*>(pre);
    const float4* r4 = reinterpret_cast<const float4*>(real);
    float* mask_out = out + 6;

    float s[4] = {0.f, 0.f, 0.f, 0.f};
    float c[4] = {0.f, 0.f, 0.f, 0.f};

    if (ts < te_staged) {
        // Preload tile ts (aligned float4 reads, streaming).
        int g0 = 256 * ts + tid;
        float4 p = __ldcs(p4 + g0);
        float4 r = __ldcs(r4 + g0);

        for (int tau = ts; tau < te_staged; tau++) {
            // Prefetch next tile's group (depth-1 pipeline).
            float4 pn = p, rn = r;
            if (tau + 1 < te_staged) {
                int gn = 256 * (tau + 1) + tid;
                pn = __ldcs(p4 + gn);
                rn = __ldcs(r4 + gn);
            }

            float om[4];
            proc4(p, r, s, c, om);

            // Buffer (tau%3) reuse gate: store of tile tau-3 (issued at
            // iteration tau-2) must be done. wait_read<1> leaves only the
            // newest pending group (tile tau-2, a different buffer).
            if (tid == 0) bulk_wait_read<1>();
            __syncthreads();

            const int buf = tau % 3;
            if (tid > 0) {
                *reinterpret_cast<float2*>(&stg[buf][4 * tid - 2]) =
                    make_float2(om[0], om[1]);
                *reinterpret_cast<float2*>(&stg[buf][4 * tid]) =
                    make_float2(om[2], om[3]);
            } else {
                *reinterpret_cast<float2*>(&stg[buf][0]) =
                    make_float2(om[2], om[3]);
                if (tau > ts) {
                    // Previous tile's tail slots.
                    *reinterpret_cast<float2*>(&stg[(tau - 1) % 3][1022]) =
                        make_float2(om[0], om[1]);
                } else if (tau == 0) {
                    // Global head: elements 0,1 -> out[6],out[7] (8B aligned).
                    __stcs(reinterpret_cast<float2*>(mask_out),
                           make_float2(om[0], om[1]));
                }
                // else: discarded — previous CTA's closing group covers it.

                if (tau + 1 == te_staged) {
                    // Closing group: om-only (dummy accumulators), fills this
                    // tile's tail slots. Group 256*(tau+1) < n/4 always here.
                    int gc = 256 * (tau + 1);
                    float4 pc = __ldcs(p4 + gc);
                    float4 rc = __ldcs(r4 + gc);
                    float sd[4] = {0.f, 0.f, 0.f, 0.f};
                    float cd[4] = {0.f, 0.f, 0.f, 0.f};
                    float omc[4];
                    proc4(pc, rc, sd, cd, omc);
                    *reinterpret_cast<float2*>(&stg[buf][1022]) =
                        make_float2(omc[0], omc[1]);
                }
            }
            __syncthreads();

            if (tid == 0) {
                fence_async();
                if (tau > ts) {
                    bulk_s2g(mask_out + 2 + 1024 * (size_t)(tau - 1),
                             smem_u32(&stg[(tau - 1) % 3][0]), 4096);
                    bulk_commit();
                }
                if (tau + 1 == te_staged) {   // this tile is now complete too
                    bulk_s2g(mask_out + 2 + 1024 * (size_t)tau,
                             smem_u32(&stg[buf][0]), 4096);
                    bulk_commit();
                }
            }
            p = pn; r = rn;
        }
    }

    // Final tile: direct streaming stores (om[0..1] of thread 0 duplicate
    // tile last_tile-1's bulk-stored tail with identical values — benign).
    if (te > last_tile) {
        int g = 256 * last_tile + tid;
        float4 p = __ldcs(p4 + g);
        float4 r = __ldcs(r4 + g);
        float om[4];
        proc4(p, r, s, c, om);
        float2* mo = reinterpret_cast<float2*>(mask_out + 4ull * (unsigned)g);
        __stcs(mo,     make_float2(om[0], om[1]));
        __stcs(mo + 1, make_float2(om[2], om[3]));
    }

    // Scalar tail (n % 1024 != 0; empty for this shape).
    if (b == 0 && tid == 0) {
        for (int e = tiles_total * TILE_ELTS; e < n; e++) {
            float om;
            classify(pre[e], real[e], s, c, om);
            mask_out[e] = om;
        }
    }

    // Drain bulk stores before exit.
    if (tid == 0) bulk_wait_all();

    // ---- Reduction: warp shuffle -> shared -> per-block atomics ----
    #pragma unroll
    for (int off = 16; off > 0; off >>= 1) {
        #pragma unroll
        for (int k = 0; k < 4; k++) {
            s[k] += __shfl_down_sync(0xffffffffu, s[k], off);
            c[k] += __shfl_down_sync(0xffffffffu, c[k], off);
        }
    }

    __shared__ float ss[4][8];
    __shared__ float sc[4][8];
    int wid  = tid >> 5;
    int lane = tid & 31;
    if (lane == 0) {
        #pragma unroll
        for (int k = 0; k < 4; k++) { ss[k][wid] = s[k]; sc[k][wid] = c[k]; }
    }
    __syncthreads();

    __shared__ bool s_is_last;
    if (tid == 0) s_is_last = false;

    if (wid == 0) {
        #pragma unroll
        for (int k = 0; k < 4; k++) {
            float v  = (lane < 8) ? ss[k][lane] : 0.f;
            float cv = (lane < 8) ? sc[k][lane] : 0.f;
            #pragma unroll
            for (int off = 4; off > 0; off >>= 1) {
                v  += __shfl_down_sync(0xffffffffu, v,  off);
                cv += __shfl_down_sync(0xffffffffu, cv, off);
            }
            if (lane == 0) {
                atomicAdd(&g_sums[k], v);
                atomicAdd(&g_cnts[k], cv);
            }
        }
        if (lane == 0) {
            __threadfence();
            unsigned int ticket = atomicAdd(&g_done, 1u);
            if (ticket == gridDim.x - 1) s_is_last = true;
        }
    }
    __syncthreads();

    // ---- Last block finalizes and resets state for the next replay ----
    if (s_is_last && tid == 0) {
        __threadfence();
        float sv[4], cv[4];
        float s0 = 0.f, c0 = 0.f;
        #pragma unroll
        for (int k = 0; k < 4; k++) {
            sv[k] = g_sums[k]; cv[k] = g_cnts[k];
            s0 += sv[k]; c0 += cv[k];           // class 0 = union (exact)
            g_sums[k] = 0.f; g_cnts[k] = 0.f;   // reset for next replay
        }
        float l0 = (c0 == 0.f) ? 0.f : (s0 / c0) * 0.2f;
        out[1] = l0;
        float tot = l0;
        #pragma unroll
        for (int k = 0; k < 4; k++) {
            float lk = (cv[k] == 0.f) ? 0.f : (sv[k] / cv[k]) * 0.2f;
            out[2 + k] = lk;
            tot += lk;
        }
        out[0] = tot;
        g_done = 0u;
        __threadfence();
    }
}

extern "C" void kernel_launch(void* const* d_in, const int* in_sizes, int n_in,
                              void* d_out, int out_size) {
    const float* pre  = (const float*)d_in[0];
    const float* real = (const float*)d_in[1];
    float* out = (float*)d_out;

    int n           = in_sizes[0];
    int tiles_total = n / TILE_ELTS;

    mcl_bulk_kernel<<<GRID, NT>>>(pre, real, out, tiles_total, n);
}